// round 10
// baseline (speedup 1.0000x reference)
#include <cuda_runtime.h>
#include <cuda_bf16.h>
#include <cstdint>

#define N_ITEMS 100000
#define HID 128
#define NNZ_N 1600000

// Intermediate: support = X @ W^T + b   (51.2 MB device-global scratch)
__device__ float g_support[(size_t)N_ITEMS * HID];
__device__ int   g_row_start[N_ITEMS + 1];   // CSR row pointers

// ---------------------------------------------------------------------------
// PTX helpers (all stable ISA — valid for plain sm_103 ptxas target)
// ---------------------------------------------------------------------------
__device__ __forceinline__ uint32_t smem_u32(const void* p) {
    uint32_t a;
    asm("{ .reg .u64 t; cvta.to.shared.u64 t, %1; cvt.u32.u64 %0, t; }"
        : "=r"(a) : "l"(p));
    return a;
}

__device__ __forceinline__ void ldsm4(uint32_t* r, uint32_t addr) {
    asm volatile("ldmatrix.sync.aligned.m8n8.x4.shared.b16 {%0,%1,%2,%3}, [%4];"
        : "=r"(r[0]), "=r"(r[1]), "=r"(r[2]), "=r"(r[3]) : "r"(addr));
}

__device__ __forceinline__ void mma16816(float* d, const uint32_t* a,
                                         uint32_t b0, uint32_t b1) {
    asm volatile("mma.sync.aligned.m16n8k16.row.col.f32.bf16.bf16.f32 "
        "{%0,%1,%2,%3}, {%4,%5,%6,%7}, {%8,%9}, {%0,%1,%2,%3};"
        : "+f"(d[0]), "+f"(d[1]), "+f"(d[2]), "+f"(d[3])
        : "r"(a[0]), "r"(a[1]), "r"(a[2]), "r"(a[3]), "r"(b0), "r"(b1));
}

// Split a float4 into hi/lo bf16x4 (8B each). hi = rn(bf16); lo = rn(x - hi).
__device__ __forceinline__ void split4(float4 v, uint2& hu, uint2& lu) {
    __nv_bfloat16 h0 = __float2bfloat16(v.x), h1 = __float2bfloat16(v.y);
    __nv_bfloat16 h2 = __float2bfloat16(v.z), h3 = __float2bfloat16(v.w);
    __nv_bfloat16 l0 = __float2bfloat16(v.x - __bfloat162float(h0));
    __nv_bfloat16 l1 = __float2bfloat16(v.y - __bfloat162float(h1));
    __nv_bfloat16 l2 = __float2bfloat16(v.z - __bfloat162float(h2));
    __nv_bfloat16 l3 = __float2bfloat16(v.w - __bfloat162float(h3));
    __nv_bfloat162 hp0 = {h0, h1}, hp1 = {h2, h3};
    __nv_bfloat162 lp0 = {l0, l1}, lp1 = {l2, l3};
    hu.x = *(uint32_t*)&hp0; hu.y = *(uint32_t*)&hp1;
    lu.x = *(uint32_t*)&lp0; lu.y = *(uint32_t*)&lp1;
}

// ---------------------------------------------------------------------------
// GEMM: support = X @ W^T + b via bf16 2-split mma.sync, fp32 accumulate.
// CTA tile 256m x 128n, K=128; 512 threads = 16 warps (8m x 2n),
// warp tile 32m x 64n (unchanged from the validated R9 config).
// smem rows padded to 136 bf16 (272 B) -> ldmatrix conflict-free.
// ---------------------------------------------------------------------------
#define SA 136
#define TM 256                       // CTA rows
#define A_TILE_E (TM * SA)
#define B_TILE_E (128 * SA)
#define GEMM_SMEM ((2 * A_TILE_E + 2 * B_TILE_E) * 2)   // 208896 B

extern "C" __global__ void __launch_bounds__(512, 1)
gemm_mma_kernel(const float* __restrict__ X, const float* __restrict__ W,
                const float* __restrict__ bias, int nrows)
{
    extern __shared__ __nv_bfloat16 sm[];
    __nv_bfloat16* Ah = sm;
    __nv_bfloat16* Al = Ah + A_TILE_E;
    __nv_bfloat16* Bh = Al + A_TILE_E;
    __nv_bfloat16* Bl = Bh + B_TILE_E;

    const int tid  = threadIdx.x;
    const int lane = tid & 31;
    const int wid  = tid >> 5;
    const int row0 = blockIdx.x * TM;

    // ---- load + split-convert X tile (256 rows) and W (128 rows) ----
    {
        // X: 512 threads, 2 threads/row, 16 float4 each.
        const int r    = tid >> 1;
        const int c0   = (tid & 1) * 64;
        const int grow = row0 + r;
        const bool ok  = grow < nrows;
        const float4* xp = (const float4*)(X + (size_t)grow * HID + c0);
        #pragma unroll
        for (int j = 0; j < 16; j++) {
            float4 xv = ok ? xp[j] : make_float4(0.f, 0.f, 0.f, 0.f);
            uint2 hu, lu;
            split4(xv, hu, lu);
            int off = r * SA + c0 + j * 4;
            *(uint2*)(Ah + off) = hu;
            *(uint2*)(Al + off) = lu;
        }
        // W: 512 threads, 4 threads/row, 8 float4 each.
        const int wr  = tid >> 2;
        const int wc0 = (tid & 3) * 32;
        const float4* wp = (const float4*)(W + (size_t)wr * HID + wc0);
        #pragma unroll
        for (int j = 0; j < 8; j++) {
            float4 wv = wp[j];
            uint2 hu, lu;
            split4(wv, hu, lu);
            int off = wr * SA + wc0 + j * 4;
            *(uint2*)(Bh + off) = hu;
            *(uint2*)(Bl + off) = lu;
        }
    }
    __syncthreads();

    // ---- mma mainloop: 3 split passes (AhBh, AhBl, AlBh) x 8 k16 steps ----
    const int wm = (wid & 7) * 32;       // warp m offset (0..224)
    const int wn = (wid >> 3) * 64;      // warp n offset (0/64)

    float acc[2][8][4];
    #pragma unroll
    for (int i = 0; i < 2; i++)
        #pragma unroll
        for (int j = 0; j < 8; j++)
            #pragma unroll
            for (int q = 0; q < 4; q++) acc[i][j][q] = 0.f;

    // per-lane element offsets (in bf16 units) for ldmatrix.x4
    const uint32_t a_lane = (uint32_t)((wm + (lane & 15)) * SA + ((lane >> 4) << 3));
    const uint32_t b_lane = (uint32_t)((wn + ((lane >> 4) << 3) + (lane & 7)) * SA
                                       + (((lane >> 3) & 1) << 3));
    const uint32_t ah_b = smem_u32(Ah), al_b = smem_u32(Al);
    const uint32_t bh_b = smem_u32(Bh), bl_b = smem_u32(Bl);

    #pragma unroll 1
    for (int s = 0; s < 3; s++) {
        const uint32_t Ab = (s == 2) ? al_b : ah_b;
        const uint32_t Bb = (s == 1) ? bl_b : bh_b;
        #pragma unroll
        for (int k = 0; k < 128; k += 16) {
            uint32_t ra[2][4], rb[4][4];
            uint32_t aaddr = Ab + (a_lane + k) * 2;
            ldsm4(ra[0], aaddr);
            ldsm4(ra[1], aaddr + 16 * SA * 2);
            uint32_t baddr = Bb + (b_lane + k) * 2;
            #pragma unroll
            for (int g = 0; g < 4; g++)
                ldsm4(rb[g], baddr + g * 16 * SA * 2);
            #pragma unroll
            for (int mi = 0; mi < 2; mi++)
                #pragma unroll
                for (int g = 0; g < 4; g++) {
                    mma16816(acc[mi][2 * g],     ra[mi], rb[g][0], rb[g][1]);
                    mma16816(acc[mi][2 * g + 1], ra[mi], rb[g][2], rb[g][3]);
                }
        }
    }

    // ---- epilogue: add bias, write fp32 support ----
    const int lrow = lane >> 2;
    const int lcol = (lane & 3) * 2;
    float2 bv[8];
    #pragma unroll
    for (int nj = 0; nj < 8; nj++) {
        int c = wn + nj * 8 + lcol;
        bv[nj].x = __ldg(bias + c);
        bv[nj].y = __ldg(bias + c + 1);
    }
    #pragma unroll
    for (int mi = 0; mi < 2; mi++) {
        int r1 = row0 + wm + mi * 16 + lrow;
        int r2 = r1 + 8;
        #pragma unroll
        for (int nj = 0; nj < 8; nj++) {
            int c = wn + nj * 8 + lcol;
            if (r1 < nrows) {
                float2 o = {acc[mi][nj][0] + bv[nj].x, acc[mi][nj][1] + bv[nj].y};
                *(float2*)&g_support[(size_t)r1 * HID + c] = o;
            }
            if (r2 < nrows) {
                float2 o = {acc[mi][nj][2] + bv[nj].x, acc[mi][nj][3] + bv[nj].y};
                *(float2*)&g_support[(size_t)r2 * HID + c] = o;
            }
        }
    }
}

// ---------------------------------------------------------------------------
// Row-pointer build: adj_rows sorted -> O(NNZ) boundary scan.
// ---------------------------------------------------------------------------
extern "C" __global__ void __launch_bounds__(256)
rowstart_kernel(const int* __restrict__ rows)
{
    int i = blockIdx.x * blockDim.x + threadIdx.x;
    if (i >= NNZ_N) return;
    int cur  = __ldg(rows + i);
    int prev = (i == 0) ? -1 : __ldg(rows + i - 1);
    for (int r = prev + 1; r <= cur; r++) g_row_start[r] = i;
    if (i == NNZ_N - 1)
        for (int r = cur + 1; r <= N_ITEMS; r++) g_row_start[r] = NNZ_N;
}

// ---------------------------------------------------------------------------
// SpMM: one warp per 8 rows. Lane covers 4 columns (float4 gather);
// edge (c,v) loaded 32-wide then shfl-broadcast. No searches, no atomics,
// deterministic in-order accumulation.  (Measured-good in R8/R9.)
// ---------------------------------------------------------------------------
#define WR 8   // rows per warp

extern "C" __global__ void __launch_bounds__(256)
spmm_kernel(const int* __restrict__ cols, const float* __restrict__ vals,
            float* __restrict__ out)
{
    const int lane = threadIdx.x & 31;
    const int wg   = blockIdx.x * 8 + (threadIdx.x >> 5);
    const int r0   = wg * WR;
    if (r0 >= N_ITEMS) return;
    const int rend = min(r0 + WR, N_ITEMS);
    const float* sp = g_support + lane * 4;

    for (int r = r0; r < rend; r++) {
        const int s = g_row_start[r];
        const int e = g_row_start[r + 1];
        float4 acc = make_float4(0.f, 0.f, 0.f, 0.f);

        for (int i = s; i < e; ) {
            const int m = min(32, e - i);
            int   cc = 0;
            float vv = 0.f;
            if (lane < m) { cc = __ldg(cols + i + lane); vv = __ldg(vals + i + lane); }

            int u = 0;
            for (; u + 4 <= m; u += 4) {
                int c0 = __shfl_sync(0xFFFFFFFFu, cc, u);
                int c1 = __shfl_sync(0xFFFFFFFFu, cc, u + 1);
                int c2 = __shfl_sync(0xFFFFFFFFu, cc, u + 2);
                int c3 = __shfl_sync(0xFFFFFFFFu, cc, u + 3);
                float4 g0 = *(const float4*)(sp + (size_t)c0 * HID);
                float4 g1 = *(const float4*)(sp + (size_t)c1 * HID);
                float4 g2 = *(const float4*)(sp + (size_t)c2 * HID);
                float4 g3 = *(const float4*)(sp + (size_t)c3 * HID);
                float v0 = __shfl_sync(0xFFFFFFFFu, vv, u);
                float v1 = __shfl_sync(0xFFFFFFFFu, vv, u + 1);
                float v2 = __shfl_sync(0xFFFFFFFFu, vv, u + 2);
                float v3 = __shfl_sync(0xFFFFFFFFu, vv, u + 3);
                acc.x = fmaf(v0, g0.x, acc.x); acc.y = fmaf(v0, g0.y, acc.y);
                acc.z = fmaf(v0, g0.z, acc.z); acc.w = fmaf(v0, g0.w, acc.w);
                acc.x = fmaf(v1, g1.x, acc.x); acc.y = fmaf(v1, g1.y, acc.y);
                acc.z = fmaf(v1, g1.z, acc.z); acc.w = fmaf(v1, g1.w, acc.w);
                acc.x = fmaf(v2, g2.x, acc.x); acc.y = fmaf(v2, g2.y, acc.y);
                acc.z = fmaf(v2, g2.z, acc.z); acc.w = fmaf(v2, g2.w, acc.w);
                acc.x = fmaf(v3, g3.x, acc.x); acc.y = fmaf(v3, g3.y, acc.y);
                acc.z = fmaf(v3, g3.z, acc.z); acc.w = fmaf(v3, g3.w, acc.w);
            }
            for (; u < m; u++) {
                int   c = __shfl_sync(0xFFFFFFFFu, cc, u);
                float v = __shfl_sync(0xFFFFFFFFu, vv, u);
                float4 g = *(const float4*)(sp + (size_t)c * HID);
                acc.x = fmaf(v, g.x, acc.x); acc.y = fmaf(v, g.y, acc.y);
                acc.z = fmaf(v, g.z, acc.z); acc.w = fmaf(v, g.w, acc.w);
            }
            i += m;
        }
        *(float4*)(out + (size_t)r * HID + lane * 4) = acc;
    }
}

// ---------------------------------------------------------------------------
extern "C" void kernel_launch(void* const* d_in, const int* in_sizes, int n_in,
                              void* d_out, int out_size) {
    const float* X  = (const float*)d_in[0];  // [100000, 128]
    const int*   ar = (const int*)  d_in[1];  // adj_rows (sorted)
    const int*   ac = (const int*)  d_in[2];  // adj_cols
    const float* av = (const float*)d_in[3];  // adj_vals
    const float* W  = (const float*)d_in[4];  // [128, 128] (out, in)
    const float* b  = (const float*)d_in[5];  // [128]
    float* out = (float*)d_out;               // [100000, 128]

    cudaFuncSetAttribute(gemm_mma_kernel,
                         cudaFuncAttributeMaxDynamicSharedMemorySize, GEMM_SMEM);

    const int gblocks = (N_ITEMS + TM - 1) / TM;             // 391
    gemm_mma_kernel<<<gblocks, 512, GEMM_SMEM>>>(X, W, b, N_ITEMS);

    rowstart_kernel<<<(NNZ_N + 255) / 256, 256>>>(ar);

    const int sblocks = (N_ITEMS + 8 * WR - 1) / (8 * WR);   // 1563
    spmm_kernel<<<sblocks, 256>>>(ac, av, out);
}